// round 17
// baseline (speedup 1.0000x reference)
#include <cuda_runtime.h>
#include <math.h>

// Problem constants
#define NV 35709
#define NF 70789
#define NB 64
#define TN (3*NV)          // 107127
#define KC 224             // 80 id + 64 ex + 80 tex coeff columns

#define GEMM_SMEM ((KC*NB + 128*65) * 4)   // 57344 + 33280 bytes = 90624

typedef unsigned long long u64;

// packed f32x2 FMA: each 32-bit lane is an independent correctly-rounded FMA,
// so per-output accumulation order (ascending k) is bitwise-identical to FFMA.
#define FMA2(acc, a, b) asm("fma.rn.f32x2 %0, %1, %2, %0;" : "+l"(acc) : "l"(a), "l"(b))

__device__ __forceinline__ u64 pack2(float s) {
    u64 d; unsigned v = __float_as_uint(s);
    asm("mov.b64 %0, {%1, %1};" : "=l"(d) : "r"(v));
    return d;
}
__device__ __forceinline__ void unpack2(u64 p, float& lo, float& hi) {
    unsigned a, b;
    asm("mov.b64 {%0, %1}, %2;" : "=r"(a), "=r"(b) : "l"(p));
    lo = __uint_as_float(a); hi = __uint_as_float(b);
}

// ---------------- scratch (static __device__ — no allocations) ----------------
__device__ float d_cT[KC*NB];                    // transposed coeffs
__device__ float d_rotM[NB*9];                   // per-batch rotation
__device__ float d_gg[NB*27];                    // SH gains
__device__ float d_Sx[(size_t)NV*NB];            // shape planes (v*64+b)
__device__ float d_Sy[(size_t)NV*NB];
__device__ float d_Sz[(size_t)NV*NB];
__device__ float d_txR[(size_t)NV*NB];           // texture planes (/255)
__device__ float d_txG[(size_t)NV*NB];
__device__ float d_txB[(size_t)NV*NB];
__device__ float d_fnx[(size_t)(NF+1)*NB];       // face-normal planes (+zero row)
__device__ float d_fny[(size_t)(NF+1)*NB];
__device__ float d_fnz[(size_t)(NF+1)*NB];
__device__ int4  d_face4[NF];                    // padded face indices

// ---------------- kernel 0: setup + face padding (merged) ---------------------
__global__ void setup_k(const float* __restrict__ coeffs,
                        const float* __restrict__ init_lit,
                        const int* __restrict__ face_buf)
{
    int gtid = blockIdx.x * blockDim.x + threadIdx.x;
    if (gtid < NF)
        d_face4[gtid] = make_int4(face_buf[gtid*3], face_buf[gtid*3+1], face_buf[gtid*3+2], 0);
    if (blockIdx.x == 0) {
        int tid = threadIdx.x;
        for (int idx = tid; idx < KC*NB; idx += blockDim.x) {
            int k = idx >> 6, b = idx & 63;
            d_cT[idx] = coeffs[b*257 + k];
        }
        for (int idx = tid; idx < NB*27; idx += blockDim.x) {
            int b = idx / 27, r = idx % 27;
            int k = r / 3, c = r % 3;
            d_gg[idx] = coeffs[b*257 + 227 + c*9 + k] + init_lit[k];
        }
        if (tid < NB) {
            int b = tid;
            float ax = coeffs[b*257+224], ay = coeffs[b*257+225], az = coeffs[b*257+226];
            float cx = cosf(ax), sx = sinf(ax);
            float cy = cosf(ay), sy = sinf(ay);
            float cz = cosf(az), sz = sinf(az);
            float* M = d_rotM + b*9;
            M[0] = cz*cy;  M[1] = cz*sy*sx - sz*cx;  M[2] = cz*sy*cx + sz*sx;
            M[3] = sz*cy;  M[4] = sz*sy*sx + cz*cx;  M[5] = sz*sy*cx - cz*sx;
            M[6] = -sy;    M[7] = cy*sx;             M[8] = cy*cx;
        }
    }
}

// ---------------- kernel 1: fused shape + texture GEMM ------------------------
// Reference fp op order: shape = (idGemm + exGemm) + meanshape, each GEMM an
// ascending-k FFMA chain from acc=0. f32x2 packs two BATCH lanes per op.
// cT staged in shared memory (LDS pipe, hoistable) to unclog the LSU queue;
// bv stream register double-buffered to hide L2/DRAM latency.
__global__ __launch_bounds__(256, 2) void gemm_k(
    const float* __restrict__ idBase, const float* __restrict__ exBase,
    const float* __restrict__ texBase, const float* __restrict__ meanshape,
    const float* __restrict__ meantex)
{
    extern __shared__ float smem[];
    float* sc = smem;              // [KC*NB]  staged coeffs
    float* T  = smem + KC*NB;      // [128*65] transpose buffer

    const int tid = threadIdx.x;
    const int tr = tid >> 3, tb = tid & 7;
    const int rowBase = blockIdx.x << 7;
    const int r0 = rowBase + tr*4;
    const bool rowOK[4] = { r0 < TN, r0+1 < TN, r0+2 < TN, r0+3 < TN };

    // stage cT: coalesced float4 copies (KC*NB/4 = 3584 float4s)
    for (int i = tid; i < KC*NB/4; i += 256)
        ((float4*)sc)[i] = ((const float4*)d_cT)[i];
    __syncthreads();
    const float* scB = sc + tb*8;

    u64 acc1[4][4], acc2[4][4];
    #pragma unroll
    for (int rr = 0; rr < 4; rr++)
        #pragma unroll
        for (int p = 0; p < 4; p++) { acc1[rr][p] = 0ull; acc2[rr][p] = 0ull; }

    float4 bv[4], bvn[4];

    // --- id base: K = 80 -> acc1
    #pragma unroll
    for (int rr = 0; rr < 4; rr++)
        bv[rr] = rowOK[rr] ? *(const float4*)(idBase + (size_t)(r0+rr)*80)
                           : make_float4(0.f,0.f,0.f,0.f);
    #pragma unroll 2
    for (int k = 0; k < 80; k += 4) {
        if (k + 4 < 80) {
            #pragma unroll
            for (int rr = 0; rr < 4; rr++)
                bvn[rr] = rowOK[rr] ? *(const float4*)(idBase + (size_t)(r0+rr)*80 + k + 4)
                                    : make_float4(0.f,0.f,0.f,0.f);
        }
        #pragma unroll
        for (int q = 0; q < 4; q++) {
            ulonglong2 cA = *(const ulonglong2*)(scB + (k+q)*64);
            ulonglong2 cB = *(const ulonglong2*)(scB + (k+q)*64 + 4);
            #pragma unroll
            for (int rr = 0; rr < 4; rr++) {
                u64 a2 = pack2(((const float*)&bv[rr])[q]);
                FMA2(acc1[rr][0], a2, cA.x);
                FMA2(acc1[rr][1], a2, cA.y);
                FMA2(acc1[rr][2], a2, cB.x);
                FMA2(acc1[rr][3], a2, cB.y);
            }
        }
        #pragma unroll
        for (int rr = 0; rr < 4; rr++) bv[rr] = bvn[rr];
    }

    // --- ex base: K = 64 -> acc2 (separately rounded GEMM)
    #pragma unroll
    for (int rr = 0; rr < 4; rr++)
        bv[rr] = rowOK[rr] ? *(const float4*)(exBase + (size_t)(r0+rr)*64)
                           : make_float4(0.f,0.f,0.f,0.f);
    #pragma unroll 2
    for (int k = 0; k < 64; k += 4) {
        if (k + 4 < 64) {
            #pragma unroll
            for (int rr = 0; rr < 4; rr++)
                bvn[rr] = rowOK[rr] ? *(const float4*)(exBase + (size_t)(r0+rr)*64 + k + 4)
                                    : make_float4(0.f,0.f,0.f,0.f);
        }
        #pragma unroll
        for (int q = 0; q < 4; q++) {
            ulonglong2 cA = *(const ulonglong2*)(scB + (80+k+q)*64);
            ulonglong2 cB = *(const ulonglong2*)(scB + (80+k+q)*64 + 4);
            #pragma unroll
            for (int rr = 0; rr < 4; rr++) {
                u64 a2 = pack2(((const float*)&bv[rr])[q]);
                FMA2(acc2[rr][0], a2, cA.x);
                FMA2(acc2[rr][1], a2, cA.y);
                FMA2(acc2[rr][2], a2, cB.x);
                FMA2(acc2[rr][3], a2, cB.y);
            }
        }
        #pragma unroll
        for (int rr = 0; rr < 4; rr++) bv[rr] = bvn[rr];
    }

    // shape = (id + ex) + ms, exact reference op order
    float ms[4];
    #pragma unroll
    for (int rr = 0; rr < 4; rr++)
        ms[rr] = rowOK[rr] ? meanshape[r0+rr] : 0.f;
    #pragma unroll
    for (int rr = 0; rr < 4; rr++)
        #pragma unroll
        for (int p = 0; p < 4; p++) {
            float i0, i1, e0, e1;
            unpack2(acc1[rr][p], i0, i1);
            unpack2(acc2[rr][p], e0, e1);
            T[(tr*4+rr)*65 + tb*8 + 2*p]     = __fadd_rn(__fadd_rn(i0, e0), ms[rr]);
            T[(tr*4+rr)*65 + tb*8 + 2*p + 1] = __fadd_rn(__fadd_rn(i1, e1), ms[rr]);
        }
    __syncthreads();
    for (int i = tid; i < 128*64; i += 256) {
        int b = i & 63, r = i >> 6;
        int row = rowBase + r;
        if (row < TN) {
            int v = row / 3, c = row - 3*v;
            float* pl = (c == 0) ? d_Sx : (c == 1) ? d_Sy : d_Sz;
            pl[(size_t)v*64 + b] = T[r*65 + b];
        }
    }
    __syncthreads();

    // --- tex base: K = 80 -> reuse acc1
    #pragma unroll
    for (int rr = 0; rr < 4; rr++)
        #pragma unroll
        for (int p = 0; p < 4; p++) acc1[rr][p] = 0ull;
    #pragma unroll
    for (int rr = 0; rr < 4; rr++)
        bv[rr] = rowOK[rr] ? *(const float4*)(texBase + (size_t)(r0+rr)*80)
                           : make_float4(0.f,0.f,0.f,0.f);
    #pragma unroll 2
    for (int k = 0; k < 80; k += 4) {
        if (k + 4 < 80) {
            #pragma unroll
            for (int rr = 0; rr < 4; rr++)
                bvn[rr] = rowOK[rr] ? *(const float4*)(texBase + (size_t)(r0+rr)*80 + k + 4)
                                    : make_float4(0.f,0.f,0.f,0.f);
        }
        #pragma unroll
        for (int q = 0; q < 4; q++) {
            ulonglong2 cA = *(const ulonglong2*)(scB + (144+k+q)*64);
            ulonglong2 cB = *(const ulonglong2*)(scB + (144+k+q)*64 + 4);
            #pragma unroll
            for (int rr = 0; rr < 4; rr++) {
                u64 a2 = pack2(((const float*)&bv[rr])[q]);
                FMA2(acc1[rr][0], a2, cA.x);
                FMA2(acc1[rr][1], a2, cA.y);
                FMA2(acc1[rr][2], a2, cB.x);
                FMA2(acc1[rr][3], a2, cB.y);
            }
        }
        #pragma unroll
        for (int rr = 0; rr < 4; rr++) bv[rr] = bvn[rr];
    }
    float mt[4];
    #pragma unroll
    for (int rr = 0; rr < 4; rr++)
        mt[rr] = rowOK[rr] ? meantex[r0+rr] : 0.f;
    #pragma unroll
    for (int rr = 0; rr < 4; rr++)
        #pragma unroll
        for (int p = 0; p < 4; p++) {
            float t0, t1;
            unpack2(acc1[rr][p], t0, t1);
            T[(tr*4+rr)*65 + tb*8 + 2*p]     = __fdiv_rn(__fadd_rn(t0, mt[rr]), 255.0f);
            T[(tr*4+rr)*65 + tb*8 + 2*p + 1] = __fdiv_rn(__fadd_rn(t1, mt[rr]), 255.0f);
        }
    __syncthreads();
    for (int i = tid; i < 128*64; i += 256) {
        int b = i & 63, r = i >> 6;
        int row = rowBase + r;
        if (row < TN) {
            int v = row / 3, c = row - 3*v;
            float* pl = (c == 0) ? d_txR : (c == 1) ? d_txG : d_txB;
            pl[(size_t)v*64 + b] = T[r*65 + b];
        }
    }
}

// ---------------- kernel 2: rigid transform -> face_vertex --------------------
__global__ __launch_bounds__(256) void transform_k(const float* __restrict__ coeffs,
                                                   float* __restrict__ out)
{
    __shared__ float sm[96][65];
    const int tid = threadIdx.x;
    const int b = tid & 63;
    const int v0 = blockIdx.x * 32;
    const float* M = d_rotM + b*9;
    float m0=M[0],m1=M[1],m2=M[2],m3=M[3],m4=M[4],m5=M[5],m6=M[6],m7=M[7],m8=M[8];
    float tx = coeffs[b*257+254], ty = coeffs[b*257+255], tz = coeffs[b*257+256];
    #pragma unroll
    for (int it = 0; it < 8; it++) {
        int vl = (tid >> 6) + it*4;
        int v = v0 + vl;
        if (v < NV) {
            int si = v*64 + b;
            float x = d_Sx[si], y = d_Sy[si], z = d_Sz[si];
            float px = fmaf(m0,x, fmaf(m1,y, fmaf(m2,z, tx)));
            float py = fmaf(m3,x, fmaf(m4,y, fmaf(m5,z, ty)));
            float pz = fmaf(m6,x, fmaf(m7,y, fmaf(m8,z, tz)));
            sm[vl*3+0][b] = px;
            sm[vl*3+1][b] = py;
            sm[vl*3+2][b] = 10.0f - pz;
        }
    }
    __syncthreads();
    int nv = NV - v0; if (nv > 32) nv = 32;
    if (nv == 32) {
        #pragma unroll
        for (int j = 0; j < 24; j++) {
            int idx = tid + j*256;
            int bb = (unsigned)idx / 96u, e = idx - bb*96;
            out[((size_t)bb*NV + v0)*3 + e] = sm[e][bb];
        }
    } else {
        int ne = 3*nv;
        for (int idx = tid; idx < 64*ne; idx += 256) {
            int bb = idx / ne, e = idx - bb*ne;
            out[((size_t)bb*NV + v0)*3 + e] = sm[e][bb];
        }
    }
}

// ---------------- kernel 3: per-face normals ----------------------------------
// Cross product replicates XLA/LLVM's FMA contraction: fma(ay,bz, -(az*by)).
// 32-bit index math throughout (all offsets < 2^31).
__global__ __launch_bounds__(256) void fnorm_k()
{
    int tid = threadIdx.x;
    int b = tid & 63;
    int f = blockIdx.x*4 + (tid >> 6);
    if (f > NF) return;
    int o = f*64 + b;
    if (f == NF) { d_fnx[o] = 0.f; d_fny[o] = 0.f; d_fnz[o] = 0.f; return; }
    int4 vi = d_face4[f];
    int i0 = vi.x*64 + b, i1 = vi.y*64 + b, i2 = vi.z*64 + b;
    float p0x = d_Sx[i0], p0y = d_Sy[i0], p0z = d_Sz[i0];
    float p1x = d_Sx[i1], p1y = d_Sy[i1], p1z = d_Sz[i1];
    float p2x = d_Sx[i2], p2y = d_Sy[i2], p2z = d_Sz[i2];
    float ax = __fsub_rn(p0x, p1x), ay = __fsub_rn(p0y, p1y), az = __fsub_rn(p0z, p1z);
    float bx = __fsub_rn(p1x, p2x), by = __fsub_rn(p1y, p2y), bz = __fsub_rn(p1z, p2z);
    float nx = fmaf(ay, bz, -__fmul_rn(az, by));
    float ny = fmaf(az, bx, -__fmul_rn(ax, bz));
    float nz = fmaf(ax, by, -__fmul_rn(ay, bx));
    float nrm = sqrtf(nx*nx + ny*ny + nz*nz);
    float den = fmaxf(nrm, 1e-12f);
    d_fnx[o] = __fdiv_rn(nx, den);
    d_fny[o] = __fdiv_rn(ny, den);
    d_fnz[o] = __fdiv_rn(nz, den);
}

// ---------------- kernel 4: vertex normals + SH color -------------------------
__global__ __launch_bounds__(256) void color_k(const int* __restrict__ point_buf,
                                               float* __restrict__ out)
{
    __shared__ float sm[96][65];
    const int tid = threadIdx.x;
    const int b = tid & 63;
    const int v0 = blockIdx.x * 32;
    const float* M = d_rotM + b*9;
    float m0=M[0],m1=M[1],m2=M[2],m3=M[3],m4=M[4],m5=M[5],m6=M[6],m7=M[7],m8=M[8];
    const float* g = d_gg + b*27;

    #pragma unroll
    for (int it = 0; it < 8; it++) {
        int vl = (tid >> 6) + it*4;
        int v = v0 + vl;
        if (v < NV) {
            float sx = 0.f, sy = 0.f, sz = 0.f;
            #pragma unroll
            for (int k = 0; k < 8; k++) {
                int f = point_buf[v*8 + k];        // uniform broadcast
                int idx = f*64 + b;                // coalesced, 32-bit
                sx = __fadd_rn(sx, d_fnx[idx]);
                sy = __fadd_rn(sy, d_fny[idx]);
                sz = __fadd_rn(sz, d_fnz[idx]);
            }
            float nrm = sqrtf(sx*sx + sy*sy + sz*sz);
            float den = fmaxf(nrm, 1e-12f);
            sx = __fdiv_rn(sx, den);
            sy = __fdiv_rn(sy, den);
            sz = __fdiv_rn(sz, den);
            float nx = fmaf(m0,sx, fmaf(m1,sy, m2*sz));
            float ny = fmaf(m3,sx, fmaf(m4,sy, m5*sz));
            float nz = fmaf(m6,sx, fmaf(m7,sy, m8*sz));

            float Y[9];
            Y[0] = 0.886226925452758f;
            Y[1] = -1.772453850905516f * ny;
            Y[2] =  1.772453850905516f * nz;
            Y[3] = -1.772453850905516f * nx;
            Y[4] =  2.427050983124842f * nx * ny;
            Y[5] = -2.427050983124842f * ny * nz;
            Y[6] =  0.700629269224046f * (3.0f*nz*nz - 1.0f);
            Y[7] = -2.427050983124842f * nx * nz;
            Y[8] =  1.213525491562421f * (nx*nx - ny*ny);

            float cr = 0.f, cg = 0.f, cb = 0.f;
            #pragma unroll
            for (int k = 0; k < 9; k++) {
                cr = fmaf(Y[k], g[k*3+0], cr);
                cg = fmaf(Y[k], g[k*3+1], cg);
                cb = fmaf(Y[k], g[k*3+2], cb);
            }
            int ti = v*64 + b;
            sm[vl*3+0][b] = cr * d_txR[ti];
            sm[vl*3+1][b] = cg * d_txG[ti];
            sm[vl*3+2][b] = cb * d_txB[ti];
        }
    }
    __syncthreads();
    int nv = NV - v0; if (nv > 32) nv = 32;
    size_t obase = (size_t)NB*NV*3;
    if (nv == 32) {
        #pragma unroll
        for (int j = 0; j < 24; j++) {
            int idx = tid + j*256;
            int bb = (unsigned)idx / 96u, e = idx - bb*96;
            out[obase + ((size_t)bb*NV + v0)*3 + e] = sm[e][bb];
        }
    } else {
        int ne = 3*nv;
        for (int idx = tid; idx < 64*ne; idx += 256) {
            int bb = idx / ne, e = idx - bb*ne;
            out[obase + ((size_t)bb*NV + v0)*3 + e] = sm[e][bb];
        }
    }
}

// ---------------- kernel 5: landmarks -----------------------------------------
__global__ void lm_k(const int* __restrict__ keypoints,
                     const float* __restrict__ P,
                     const float* __restrict__ fv,
                     float* __restrict__ out)
{
    int j = threadIdx.x;
    int b = blockIdx.x;
    if (j >= 68) return;
    int v = keypoints[j];
    const float* p = fv + ((size_t)b*NV + v)*3;
    float x = p[0], y = p[1], z = p[2];
    float px = x*P[0] + y*P[3] + z*P[6];
    float py = x*P[1] + y*P[4] + z*P[7];
    float pz = x*P[2] + y*P[5] + z*P[8];
    float* o = out + (size_t)2*NB*NV*3 + ((size_t)b*68 + j)*2;
    o[0] = __fdiv_rn(px, pz);
    o[1] = __fdiv_rn(py, pz);
}

// ---------------- launch -------------------------------------------------------
extern "C" void kernel_launch(void* const* d_in, const int* in_sizes, int n_in,
                              void* d_out, int out_size)
{
    const float* coeffs    = (const float*)d_in[0];
    const float* meanshape = (const float*)d_in[1];
    const float* idBase    = (const float*)d_in[2];
    const float* exBase    = (const float*)d_in[3];
    const float* meantex   = (const float*)d_in[4];
    const float* texBase   = (const float*)d_in[5];
    const float* persc     = (const float*)d_in[6];
    const float* init_lit  = (const float*)d_in[7];
    const int*   point_buf = (const int*)d_in[8];
    const int*   face_buf  = (const int*)d_in[9];
    const int*   keypoints = (const int*)d_in[10];
    float* out = (float*)d_out;

    cudaFuncSetAttribute(gemm_k, cudaFuncAttributeMaxDynamicSharedMemorySize, GEMM_SMEM);

    setup_k<<<(NF + 255)/256, 256>>>(coeffs, init_lit, face_buf);
    gemm_k<<<(TN + 127)/128, 256, GEMM_SMEM>>>(idBase, exBase, texBase, meanshape, meantex);

    transform_k<<<(NV + 31)/32, 256>>>(coeffs, out);
    fnorm_k<<<(NF + 1 + 3)/4, 256>>>();
    color_k<<<(NV + 31)/32, 256>>>(point_buf, out);

    lm_k<<<NB, 128>>>(keypoints, persc, out, out);
}